// round 2
// baseline (speedup 1.0000x reference)
#include <cuda_runtime.h>

// GCN_3831110828646 — restructured GCN:
//   a[d]  = dinv[d] * ( sum_{edges s->d} dinv[s]*x[s] + dinv[d]*x[d] )       (64-wide CSR gather)
//   z[n]  = dinv[n] * dot( relu(a[n] @ W1 + b1), W2@Wl )                     (fused GEMM+ReLU+dot)
//   out[d]= dinv[d] * ( sum_{edges s->d} z[s] + z[d] ) + (b2@Wl + bl)        (scalar CSR gather)
//
// edge_index dtype is detected at runtime (harness may deliver int64 or int32).

#define NMAX 100000
#define EMAX 1600000

__device__ int   g_idx64;                 // 1 if edge_index is int64, else int32
__device__ int   g_count[NMAX];
__device__ float g_dinv[NMAX];
__device__ int   g_off[NMAX + 1];
__device__ int   g_cur[NMAX];
__device__ int   g_csrc[EMAX];
__device__ float g_a[(size_t)NMAX * 64];
__device__ float g_z[NMAX];
__device__ float g_w2l[128];
__device__ float g_cb;

// ---------------------------------------------------------------------------
// Detect int64 vs int32 edge_index: int64 values < 2^31 have zero odd words.
__global__ void k_detect(const int* __restrict__ ei) {
    if (threadIdx.x == 0) {
        int is64 = 1;
        for (int i = 0; i < 64; i++)
            if (ei[2 * i + 1] != 0) { is64 = 0; break; }
        g_idx64 = is64;
    }
}

__device__ __forceinline__ int load_src(const void* ei, int E, int e, int n) {
    int v = g_idx64 ? (int)((const long long*)ei)[e] : ((const int*)ei)[e];
    return min(max(v, 0), n - 1);
}
__device__ __forceinline__ int load_dst(const void* ei, int E, int e, int n) {
    int v = g_idx64 ? (int)((const long long*)ei)[E + e] : ((const int*)ei)[E + e];
    return min(max(v, 0), n - 1);
}

// ---------------------------------------------------------------------------
__global__ void k_init(int n) {
    int i = blockIdx.x * blockDim.x + threadIdx.x;
    if (i < n) g_count[i] = 0;
}

__global__ void k_hist(const void* __restrict__ ei, int E, int n) {
    int e = blockIdx.x * blockDim.x + threadIdx.x;
    if (e < E) atomicAdd(&g_count[load_dst(ei, E, e, n)], 1);
}

__global__ void k_dinv(int n) {
    int i = blockIdx.x * blockDim.x + threadIdx.x;
    if (i < n) g_dinv[i] = rsqrtf((float)(g_count[i] + 1));   // deg = indeg + self-loop
}

// Single-block exclusive scan of g_count -> g_off (and g_cur copy). n <= 100k.
__global__ void k_scan(int n) {
    __shared__ int sums[1024];
    int t = threadIdx.x;
    int chunk = (n + 1023) >> 10;
    int beg = t * chunk;
    int end = min(beg + chunk, n);
    int s = 0;
    for (int i = beg; i < end; i++) s += g_count[i];
    sums[t] = s;
    __syncthreads();
    for (int d = 1; d < 1024; d <<= 1) {
        int v = (t >= d) ? sums[t - d] : 0;
        __syncthreads();
        sums[t] += v;
        __syncthreads();
    }
    int pre = (t == 0) ? 0 : sums[t - 1];
    for (int i = beg; i < end; i++) {
        int c = g_count[i];
        g_off[i] = pre;
        g_cur[i] = pre;
        pre += c;
    }
    if (t == 0) g_off[n] = sums[1023];
}

__global__ void k_fill(const void* __restrict__ ei, int E, int n) {
    int e = blockIdx.x * blockDim.x + threadIdx.x;
    if (e < E) {
        int d = load_dst(ei, E, e, n);
        int p = atomicAdd(&g_cur[d], 1);
        g_csrc[p] = load_src(ei, E, e, n);
    }
}

// ---------------------------------------------------------------------------
// Aggregation 1: one warp per dst node, 64-feature rows as float2 per lane.
__global__ void k_agg1(const float* __restrict__ x, int n) {
    int warp = (blockIdx.x * blockDim.x + threadIdx.x) >> 5;
    int lane = threadIdx.x & 31;
    if (warp >= n) return;
    int d = warp;
    float din = g_dinv[d];

    float2 acc = ((const float2*)(x + (size_t)d * 64))[lane];   // self term
    acc.x *= din; acc.y *= din;

    int off = g_off[d], end = g_off[d + 1];
    for (int base = off; base < end; base += 32) {
        int cnt = min(32, end - base);
        int s = 0; float w = 0.f;
        if (lane < cnt) {
            s = g_csrc[base + lane];
            w = g_dinv[s];
        }
        for (int j = 0; j < cnt; j++) {
            int   sj = __shfl_sync(0xffffffff, s, j);
            float wj = __shfl_sync(0xffffffff, w, j);
            float2 v = ((const float2*)(x + (size_t)sj * 64))[lane];
            acc.x += v.x * wj;
            acc.y += v.y * wj;
        }
    }
    acc.x *= din; acc.y *= din;
    ((float2*)(g_a + (size_t)d * 64))[lane] = acc;
}

// ---------------------------------------------------------------------------
// Precompute w2l = W2 @ Wl (128-vec) and cb = b2@Wl + bl.
__global__ void k_wprep(const float* __restrict__ W2, const float* __restrict__ b2,
                        const float* __restrict__ Wl, const float* __restrict__ bl) {
    int c = threadIdx.x;   // 128 threads
    float s = 0.f;
    for (int k = 0; k < 100; k++) s += W2[c * 100 + k] * Wl[k];
    g_w2l[c] = s;
    if (c == 0) {
        float t = 0.f;
        for (int k = 0; k < 100; k++) t += b2[k] * Wl[k];
        g_cb = t + bl[0];
    }
}

// ---------------------------------------------------------------------------
// Fused: z[n] = dinv[n] * dot(relu(a[n] @ W1 + b1), w2l).
// 256 threads = 8 warps; each warp processes 4 nodes (register-blocked).
__global__ void k_gemm(const float* __restrict__ W1, const float* __restrict__ b1, int n) {
    __shared__ float W1s[64 * 128];   // 32 KB
    __shared__ float b1s[128];
    __shared__ float ws[128];
    __shared__ float as[8][4][64];    // 8 KB staging of a-rows

    int tid = threadIdx.x;
    for (int i = tid; i < 2048; i += 256)
        ((float4*)W1s)[i] = ((const float4*)W1)[i];
    if (tid < 128) { b1s[tid] = b1[tid]; ws[tid] = g_w2l[tid]; }
    __syncthreads();

    int w = tid >> 5, lane = tid & 31;
    int n0 = (blockIdx.x * 8 + w) * 4;
    if (n0 >= n) return;

    // Stage 4 a-rows (clamped loads; writes guarded later)
    for (int i = lane; i < 64; i += 32) {
        int nd = i >> 4, k4 = i & 15;
        int node = min(n0 + nd, n - 1);
        ((float4*)as[w][nd])[k4] = ((const float4*)(g_a + (size_t)node * 64))[k4];
    }
    __syncwarp();

    float acc[4][4] = {};   // [node][sub-channel], channels c = 4*lane + j
    for (int k = 0; k < 64; k += 4) {
        float4 av[4];
        #pragma unroll
        for (int nd = 0; nd < 4; nd++)
            av[nd] = *(const float4*)&as[w][nd][k];
        #pragma unroll
        for (int kk = 0; kk < 4; kk++) {
            float4 wv = *(const float4*)&W1s[(k + kk) * 128 + 4 * lane];
            #pragma unroll
            for (int nd = 0; nd < 4; nd++) {
                float c = (kk == 0) ? av[nd].x : (kk == 1) ? av[nd].y
                        : (kk == 2) ? av[nd].z : av[nd].w;
                acc[nd][0] += c * wv.x;
                acc[nd][1] += c * wv.y;
                acc[nd][2] += c * wv.z;
                acc[nd][3] += c * wv.w;
            }
        }
    }

    #pragma unroll
    for (int nd = 0; nd < 4; nd++) {
        float zp = 0.f;
        #pragma unroll
        for (int j = 0; j < 4; j++) {
            int c = 4 * lane + j;
            float h = acc[nd][j] + b1s[c];
            h = fmaxf(h, 0.f);
            zp += h * ws[c];
        }
        #pragma unroll
        for (int o = 16; o; o >>= 1) zp += __shfl_xor_sync(0xffffffff, zp, o);
        int node = n0 + nd;
        if (lane == 0 && node < n) g_z[node] = g_dinv[node] * zp;
    }
}

// ---------------------------------------------------------------------------
// Scalar aggregation + epilogue: out[d] = dinv[d]*(sum_e z[src] + z[d]) + cb.
__global__ void k_agg2(float* __restrict__ out, int n) {
    int d = blockIdx.x * blockDim.x + threadIdx.x;
    if (d >= n) return;
    float s = g_z[d];   // self term (z already carries dinv[s])
    int b = g_off[d], e = g_off[d + 1];
    for (int i = b; i < e; i++) s += g_z[g_csrc[i]];
    out[d] = g_dinv[d] * s + g_cb;
}

// ---------------------------------------------------------------------------
extern "C" void kernel_launch(void* const* d_in, const int* in_sizes, int n_in,
                              void* d_out, int out_size) {
    const float* x   = (const float*)d_in[0];
    const void*  ei  = d_in[1];
    const float* W1  = (const float*)d_in[2];
    const float* b1  = (const float*)d_in[3];
    const float* W2  = (const float*)d_in[4];
    const float* b2  = (const float*)d_in[5];
    const float* Wl  = (const float*)d_in[6];
    const float* bl  = (const float*)d_in[7];
    float*       out = (float*)d_out;

    int n = in_sizes[0] / 64;
    int E = in_sizes[1] / 2;

    int nb = (n + 255) / 256;
    int eb = (E + 255) / 256;

    k_detect<<<1, 32>>>((const int*)ei);
    k_init  <<<nb, 256>>>(n);
    k_hist  <<<eb, 256>>>(ei, E, n);
    k_dinv  <<<nb, 256>>>(n);
    k_scan  <<<1, 1024>>>(n);
    k_fill  <<<eb, 256>>>(ei, E, n);
    k_wprep <<<1, 128>>>(W2, b2, Wl, bl);
    k_agg1  <<<(n + 7) / 8, 256>>>(x, n);
    k_gemm  <<<(n + 31) / 32, 256>>>(W1, b1, n);
    k_agg2  <<<nb, 256>>>(out, n);
}